// round 12
// baseline (speedup 1.0000x reference)
#include <cuda_runtime.h>
#include <cuda_bf16.h>
#include <cstdint>

// ---------------- problem constants ----------------
#define BROWS   65536
#define DDIM    1024
#define NCOLS   128      // 120 real columns padded to 128
#define KC      64       // K elems per chunk
#define NCHUNK  (DDIM / KC)   // 16
#define TILE_M  128
#define APAD    72       // smem row pitch (bf16): 144B rows -> conflict-free LDSM
#define OPAD    130      // out-tile row pitch (floats)

#define NTHREADS 320     // 8 consumer warps + 2 producer warps
#define NCONS    256
#define NPROD    64

#define ASTG    (TILE_M * APAD * 2)     // 18432 per A stage
#define BSTG    (NCOLS  * APAD * 2)     // 18432 per B stage
#define STG     (ASTG + BSTG)           // 36864
#define STAGES  3
#define SMEM_BYTES (STAGES * STG)       // 110592 (>= out tile 66560)

// packed weights: [NCOLS][DDIM] K-major bf16 (static device array — no alloc)
// rows 120..127 never written: __device__ globals are zero-initialized.
__device__ __align__(16) __nv_bfloat16 g_Wpack[NCOLS * DDIM];

__device__ __forceinline__ uint32_t smem_u32(const void* p) {
    uint32_t a;
    asm("{ .reg .u64 t; cvta.to.shared.u64 t, %1; cvt.u32.u64 %0, t; }" : "=r"(a) : "l"(p));
    return a;
}
#define CP_ASYNC16(dst_u32, src_ptr) \
    asm volatile("cp.async.cg.shared.global [%0], [%1], 16;" :: "r"(dst_u32), "l"(src_ptr) : "memory")
#define CP_COMMIT() asm volatile("cp.async.commit_group;" ::: "memory")
#define CP_WAIT0()  asm volatile("cp.async.wait_group 0;" ::: "memory")
#define LDSM_X4(r0, r1, r2, r3, addr) \
    asm volatile("ldmatrix.sync.aligned.m8n8.x4.shared.b16 {%0,%1,%2,%3}, [%4];" \
                 : "=r"(r0), "=r"(r1), "=r"(r2), "=r"(r3) : "r"(addr))
// named barriers: FULL_s = 1+s, EMPTY_s = 4+s  (0 reserved for __syncthreads)
#define BAR_SYNC(id)   asm volatile("bar.sync %0, %1;"   :: "r"(id), "n"(NTHREADS) : "memory")
#define BAR_ARRIVE(id) asm volatile("bar.arrive %0, %1;" :: "r"(id), "n"(NTHREADS) : "memory")

// ---------------- weight pack kernel (smem transpose, both sides coalesced) ----
// grid (12, 4) x 256 thr.  bx<10: expert e=bx;  bx 10,11: gate t=bx-10.
__global__ void pack_weights_kernel(const float* __restrict__ expert_w,
                                    const float* __restrict__ gate_w) {
    __shared__ float s[256][10];
    const int bx = blockIdx.x;
    const int d0 = blockIdx.y * 256;
    const int tid = threadIdx.x;
    const float* src = (bx < 10) ? expert_w + (size_t)bx * DDIM * 10
                                 : gate_w   + (size_t)(bx - 10) * DDIM * 10;
    #pragma unroll
    for (int k = 0; k < 10; ++k) {
        int idx = tid + k * 256;                  // coalesced reads
        s[idx / 10][idx % 10] = src[(size_t)d0 * 10 + idx];
    }
    __syncthreads();
    const int j0 = (bx < 10) ? bx * 10 : 100 + (bx - 10) * 10;
    #pragma unroll
    for (int r = 0; r < 10; ++r)                  // coalesced writes
        g_Wpack[(size_t)(j0 + r) * DDIM + d0 + tid] = __float2bfloat16(s[tid][r]);
}

// ---------------- fused MMoE main kernel (warp-specialized, 3-stage ring) -----
extern "C" __global__ void __launch_bounds__(NTHREADS, 2)
mmoe_main_kernel(const float* __restrict__ x,
                 const float* __restrict__ expert_b,   // [10,10]
                 const float* __restrict__ gate_b,     // [2,10]
                 const float* __restrict__ ctr_w,      // [10]
                 const float* __restrict__ ctr_b,      // [1]
                 const float* __restrict__ cvr_w,      // [10]
                 const float* __restrict__ cvr_b,      // [1]
                 float* __restrict__ out) {            // [2*B] = [ctr | cvr]
    extern __shared__ char smem[];
    const uint32_t smem_base = smem_u32(smem);
    float* outS = reinterpret_cast<float*>(smem);

    const int tid  = threadIdx.x;
    const int wid  = tid >> 5;
    const int lane = tid & 31;
    const int row0 = blockIdx.x * TILE_M;

    float acc[2][8][4];
    #pragma unroll
    for (int mt = 0; mt < 2; ++mt)
        #pragma unroll
        for (int nt = 0; nt < 8; ++nt)
            #pragma unroll
            for (int i = 0; i < 4; ++i) acc[mt][nt][i] = 0.0f;

    const int gid = lane >> 2;      // 0..7
    const int tig = lane & 3;       // 0..3
    const int warp_m = (wid & 3) * 32;
    const int warp_n = ((wid >> 2) & 1) * 64;

    if (wid >= 8) {
        // ================= PRODUCER (64 threads) =================
        const int ptid = tid - NCONS;            // 0..63
        int s = 0;
        for (int c = 0; c < NCHUNK; ++c) {
            if (c >= STAGES) BAR_SYNC(4 + s);    // stage free (consumers done c-3)
            const int k0 = c * KC;
            const uint32_t aDst = smem_base + s * STG;
            const uint32_t bDst = aDst + ASTG;

            // --- B: 16 cp.async16 per thread ---
            #pragma unroll
            for (int it = 0; it < 16; ++it) {
                const int idx = ptid + it * 64;          // 0..1023
                const int row = idx >> 3, c8 = idx & 7;
                CP_ASYNC16(bDst + (uint32_t)(row * APAD + c8 * 8) * 2,
                           g_Wpack + (size_t)row * DDIM + k0 + c8 * 8);
            }
            CP_COMMIT();

            // --- A: 32 float4 per thread, batch-4 ping-pong LDG->cvt->STS ---
            float4 pb[2][4];
            #pragma unroll
            for (int j = 0; j < 4; ++j) {
                const int idx = ptid + j * 64;
                pb[0][j] = *reinterpret_cast<const float4*>(
                    x + (size_t)(row0 + (idx >> 4)) * DDIM + k0 + (idx & 15) * 4);
            }
            #pragma unroll
            for (int b = 0; b < 8; ++b) {
                if (b < 7) {
                    #pragma unroll
                    for (int j = 0; j < 4; ++j) {
                        const int idx = ptid + ((b + 1) * 4 + j) * 64;
                        pb[(b + 1) & 1][j] = *reinterpret_cast<const float4*>(
                            x + (size_t)(row0 + (idx >> 4)) * DDIM + k0 + (idx & 15) * 4);
                    }
                }
                #pragma unroll
                for (int j = 0; j < 4; ++j) {
                    const int idx = ptid + (b * 4 + j) * 64;
                    const int row = idx >> 4, c4 = idx & 15;
                    const float4 v = pb[b & 1][j];
                    __nv_bfloat162 lo = __floats2bfloat162_rn(v.x, v.y);
                    __nv_bfloat162 hi = __floats2bfloat162_rn(v.z, v.w);
                    uint2 pk;
                    pk.x = *reinterpret_cast<uint32_t*>(&lo);
                    pk.y = *reinterpret_cast<uint32_t*>(&hi);
                    asm volatile("st.shared.v2.b32 [%0], {%1, %2};"
                                 :: "r"(aDst + (uint32_t)(row * APAD + c4 * 4) * 2),
                                    "r"(pk.x), "r"(pk.y) : "memory");
                }
            }
            CP_WAIT0();                          // B(c) landed
            BAR_ARRIVE(1 + s);                   // stage s full
            if (++s == STAGES) s = 0;
        }
    } else {
        // ================= CONSUMER (256 threads) =================
        const int wstag = wid & 3;
        const uint32_t aLdsmBase =
            (uint32_t)(warp_m + ((lane >> 3) & 1) * 8 + (lane & 7)) * (APAD * 2)
            + ((lane >> 4) & 1) * 16;
        const uint32_t bLdsmBase =
            (uint32_t)(warp_n + ((lane >> 4) & 1) * 8 + (lane & 7)) * (APAD * 2)
            + ((lane >> 3) & 1) * 16;

        int s = 0;
        for (int c = 0; c < NCHUNK; ++c) {
            BAR_SYNC(1 + s);                     // stage s full
            const uint32_t aStage = smem_base + s * STG;
            const uint32_t bStage = aStage + ASTG;

            #pragma unroll
            for (int j = 0; j < 4; ++j) {
                const int kt = (j + wstag) & 3;
                const uint32_t kOff = (uint32_t)(32 * kt);

                uint32_t afrag[2][4];
                #pragma unroll
                for (int mt = 0; mt < 2; ++mt)
                    LDSM_X4(afrag[mt][0], afrag[mt][1], afrag[mt][2], afrag[mt][3],
                            aStage + aLdsmBase + (uint32_t)(mt * 16 * APAD * 2) + kOff);

                #pragma unroll
                for (int pr = 0; pr < 4; ++pr) {
                    uint32_t b0a, b1a, b0b, b1b;
                    LDSM_X4(b0a, b1a, b0b, b1b,
                            bStage + bLdsmBase + (uint32_t)(pr * 16 * APAD * 2) + kOff);
                    #pragma unroll
                    for (int mt = 0; mt < 2; ++mt) {
                        asm volatile(
                            "mma.sync.aligned.m16n8k16.row.col.f32.bf16.bf16.f32 "
                            "{%0,%1,%2,%3}, {%4,%5,%6,%7}, {%8,%9}, {%0,%1,%2,%3};"
                            : "+f"(acc[mt][2 * pr][0]), "+f"(acc[mt][2 * pr][1]),
                              "+f"(acc[mt][2 * pr][2]), "+f"(acc[mt][2 * pr][3])
                            : "r"(afrag[mt][0]), "r"(afrag[mt][1]),
                              "r"(afrag[mt][2]), "r"(afrag[mt][3]),
                              "r"(b0a), "r"(b1a));
                        asm volatile(
                            "mma.sync.aligned.m16n8k16.row.col.f32.bf16.bf16.f32 "
                            "{%0,%1,%2,%3}, {%4,%5,%6,%7}, {%8,%9}, {%0,%1,%2,%3};"
                            : "+f"(acc[mt][2 * pr + 1][0]), "+f"(acc[mt][2 * pr + 1][1]),
                              "+f"(acc[mt][2 * pr + 1][2]), "+f"(acc[mt][2 * pr + 1][3])
                            : "r"(afrag[mt][0]), "r"(afrag[mt][1]),
                              "r"(afrag[mt][2]), "r"(afrag[mt][3]),
                              "r"(b0b), "r"(b1b));
                    }
                }
            }
            if (c < NCHUNK - STAGES) BAR_ARRIVE(4 + s);   // stage s free
            if (++s == STAGES) s = 0;
        }
    }

    __syncthreads();   // all 320: ring dead -> reuse smem as outS

    // --- scatter accumulators to fp32 out tile (consumers only) ---
    if (wid < 8) {
        #pragma unroll
        for (int mt = 0; mt < 2; ++mt) {
            #pragma unroll
            for (int nt = 0; nt < 8; ++nt) {
                const int r = warp_m + mt * 16 + gid;
                const int col = warp_n + nt * 8 + tig * 2;
                *reinterpret_cast<float2*>(outS + r * OPAD + col) =
                    make_float2(acc[mt][nt][0], acc[mt][nt][1]);
                *reinterpret_cast<float2*>(outS + (r + 8) * OPAD + col) =
                    make_float2(acc[mt][nt][2], acc[mt][nt][3]);
            }
        }
    }
    __syncthreads();

    // --- per-row epilogue: softmax gates, expert mix, sigmoid heads ---
    if (tid < TILE_M) {
        const float* rowv = outS + tid * OPAD;

        float g[2][10];
        #pragma unroll
        for (int t = 0; t < 2; ++t) {
            float sacc = 0.0f;
            #pragma unroll
            for (int e = 0; e < 10; ++e) {
                float l = rowv[100 + t * 10 + e] + gate_b[t * 10 + e];
                float ex = expf(l);
                g[t][e] = ex; sacc += ex;
            }
            float inv = 1.0f / sacc;
            #pragma unroll
            for (int e = 0; e < 10; ++e) g[t][e] *= inv;
        }

        float ti0[10], ti1[10];
        #pragma unroll
        for (int u = 0; u < 10; ++u) { ti0[u] = 0.0f; ti1[u] = 0.0f; }
        #pragma unroll
        for (int e = 0; e < 10; ++e) {
            const float g0 = g[0][e], g1 = g[1][e];
            #pragma unroll
            for (int u = 0; u < 10; ++u) {
                const int j = e * 10 + u;
                float v = fmaxf(rowv[j] + expert_b[j], 0.0f);
                ti0[u] += v * g0;
                ti1[u] += v * g1;
            }
        }

        float zc = ctr_b[0], zv = cvr_b[0];
        #pragma unroll
        for (int u = 0; u < 10; ++u) {
            zc += ti0[u] * ctr_w[u];
            zv += ti1[u] * cvr_w[u];
        }
        const int gr = row0 + tid;
        out[gr]         = 1.0f / (1.0f + expf(-zc));
        out[BROWS + gr] = 1.0f / (1.0f + expf(-zv));
    }
}

// ---------------- launch ----------------
extern "C" void kernel_launch(void* const* d_in, const int* in_sizes, int n_in,
                              void* d_out, int out_size) {
    const float* x        = (const float*)d_in[0];
    const float* expert_w = (const float*)d_in[3];
    const float* expert_b = (const float*)d_in[4];
    const float* gate_w   = (const float*)d_in[5];
    const float* gate_b   = (const float*)d_in[6];
    const float* ctr_w    = (const float*)d_in[7];
    const float* ctr_b    = (const float*)d_in[8];
    const float* cvr_w    = (const float*)d_in[9];
    const float* cvr_b    = (const float*)d_in[10];
    float* out = (float*)d_out;

    cudaFuncSetAttribute(mmoe_main_kernel,
                         cudaFuncAttributeMaxDynamicSharedMemorySize, SMEM_BYTES);

    pack_weights_kernel<<<dim3(12, 4), 256>>>(expert_w, gate_w);
    mmoe_main_kernel<<<BROWS / TILE_M, NTHREADS, SMEM_BYTES>>>(
        x, expert_b, gate_b, ctr_w, ctr_b, cvr_w, cvr_b, out);
}

// round 14
// speedup vs baseline: 1.2690x; 1.2690x over previous
#include <cuda_runtime.h>
#include <cuda_bf16.h>
#include <cstdint>

// ---------------- problem constants ----------------
#define BROWS   65536
#define DDIM    1024
#define NCOLS   128      // 120 real columns padded to 128
#define KC      64       // K elems staged per chunk
#define NCHUNK  (DDIM / KC)   // 16
#define TILE_M  128
#define APAD    72       // smem row pitch (bf16): 144B rows -> conflict-free LDSM
#define OPAD    130      // out-tile row pitch (floats)

#define ABYTES  (TILE_M * APAD * 2)     // 18432 per A buffer
#define BOFF    (2 * ABYTES)            // 36864
#define BBYTES  (NCOLS * APAD * 2)      // 18432 per B buffer
#define SMEM_BYTES (BOFF + 2 * BBYTES)  // 73728 (>= out tile 66560)

// packed weights: [NCOLS][DDIM] K-major bf16 (static device array — no alloc)
// rows 120..127 never written: __device__ globals are zero-initialized.
__device__ __align__(16) __nv_bfloat16 g_Wpack[NCOLS * DDIM];

__device__ __forceinline__ uint32_t smem_u32(const void* p) {
    uint32_t a;
    asm("{ .reg .u64 t; cvta.to.shared.u64 t, %1; cvt.u32.u64 %0, t; }" : "=r"(a) : "l"(p));
    return a;
}
#define CP_ASYNC16(dst_u32, src_ptr) \
    asm volatile("cp.async.cg.shared.global [%0], [%1], 16;" :: "r"(dst_u32), "l"(src_ptr) : "memory")
#define CP_COMMIT() asm volatile("cp.async.commit_group;" ::: "memory")
#define CP_WAIT0()  asm volatile("cp.async.wait_group 0;" ::: "memory")
#define LDSM_X4(r, addr) \
    asm volatile("ldmatrix.sync.aligned.m8n8.x4.shared.b16 {%0,%1,%2,%3}, [%4];" \
                 : "=r"((r)[0]), "=r"((r)[1]), "=r"((r)[2]), "=r"((r)[3]) : "r"(addr))
#define MMA(d, a, b0, b1) \
    asm volatile("mma.sync.aligned.m16n8k16.row.col.f32.bf16.bf16.f32 " \
                 "{%0,%1,%2,%3}, {%4,%5,%6,%7}, {%8,%9}, {%0,%1,%2,%3};" \
                 : "+f"((d)[0]), "+f"((d)[1]), "+f"((d)[2]), "+f"((d)[3]) \
                 : "r"((a)[0]), "r"((a)[1]), "r"((a)[2]), "r"((a)[3]), "r"(b0), "r"(b1))

// ---------------- weight pack kernel (smem transpose, both sides coalesced) ----
__global__ void pack_weights_kernel(const float* __restrict__ expert_w,
                                    const float* __restrict__ gate_w) {
    __shared__ float s[256][10];
    const int bx = blockIdx.x;
    const int d0 = blockIdx.y * 256;
    const int tid = threadIdx.x;
    const float* src = (bx < 10) ? expert_w + (size_t)bx * DDIM * 10
                                 : gate_w   + (size_t)(bx - 10) * DDIM * 10;
    #pragma unroll
    for (int k = 0; k < 10; ++k) {
        int idx = tid + k * 256;
        s[idx / 10][idx % 10] = src[(size_t)d0 * 10 + idx];
    }
    __syncthreads();
    const int j0 = (bx < 10) ? bx * 10 : 100 + (bx - 10) * 10;
    #pragma unroll
    for (int r = 0; r < 10; ++r)
        g_Wpack[(size_t)(j0 + r) * DDIM + d0 + tid] = __float2bfloat16(s[tid][r]);
}

// ---------------- fused MMoE main kernel (frag-pipelined mainloop) ------------
extern "C" __global__ void __launch_bounds__(256, 2)
mmoe_main_kernel(const float* __restrict__ x,
                 const float* __restrict__ expert_b,   // [10,10]
                 const float* __restrict__ gate_b,     // [2,10]
                 const float* __restrict__ ctr_w,      // [10]
                 const float* __restrict__ ctr_b,      // [1]
                 const float* __restrict__ cvr_w,      // [10]
                 const float* __restrict__ cvr_b,      // [1]
                 float* __restrict__ out) {            // [2*B] = [ctr | cvr]
    extern __shared__ char smem[];
    const uint32_t smem_base = smem_u32(smem);
    float* outS = reinterpret_cast<float*>(smem);

    const int tid  = threadIdx.x;
    const int wid  = tid >> 5;
    const int lane = tid & 31;
    const int gid  = lane >> 2;
    const int tig  = lane & 3;
    const int warp_m = (wid & 3) * 32;    // 4 warps along M
    const int warp_n = (wid >> 2) * 64;   // 2 warps along N
    const int row0 = blockIdx.x * TILE_M;
    const int wstag = wid & 3;

    const uint32_t aLdsmBase =
        (uint32_t)(warp_m + ((lane >> 3) & 1) * 8 + (lane & 7)) * (APAD * 2)
        + ((lane >> 4) & 1) * 16;
    const uint32_t bLdsmBase =
        (uint32_t)(warp_n + ((lane >> 4) & 1) * 8 + (lane & 7)) * (APAD * 2)
        + ((lane >> 3) & 1) * 16;

    const int rbase = tid >> 4;          // A rows rbase + it*16
    const int c4    = tid & 15;
    const int brb   = tid >> 3;          // B rows brb + it*32
    const int c8    = tid & 7;

    float acc[2][8][4];
    #pragma unroll
    for (int mt = 0; mt < 2; ++mt)
        #pragma unroll
        for (int nt = 0; nt < 8; ++nt)
            #pragma unroll
            for (int i = 0; i < 4; ++i) acc[mt][nt][i] = 0.0f;

    float4 av[4];                         // half-tile A staging regs (16 regs)

    auto ldgA = [&](int c, int h) {       // load half h of A chunk c into av
        const int k0 = c * KC;
        #pragma unroll
        for (int it = 0; it < 4; ++it)
            av[it] = *reinterpret_cast<const float4*>(
                x + (size_t)(row0 + rbase + (h * 4 + it) * 16) * DDIM + k0 + c4 * 4);
    };
    auto stsA = [&](int c, int h) {       // store av into A buffer (c&1), half h
        __nv_bfloat16* Ab = reinterpret_cast<__nv_bfloat16*>(smem + (c & 1) * ABYTES);
        #pragma unroll
        for (int it = 0; it < 4; ++it) {
            __nv_bfloat162 lo = __floats2bfloat162_rn(av[it].x, av[it].y);
            __nv_bfloat162 hi = __floats2bfloat162_rn(av[it].z, av[it].w);
            uint2 pk;
            pk.x = *reinterpret_cast<uint32_t*>(&lo);
            pk.y = *reinterpret_cast<uint32_t*>(&hi);
            *reinterpret_cast<uint2*>(Ab + (rbase + (h * 4 + it) * 16) * APAD + c4 * 4) = pk;
        }
    };
    auto issue_B = [&](int c) {
        const int k0 = c * KC;
        const uint32_t bb = smem_base + BOFF + (c & 1) * BBYTES;
        #pragma unroll
        for (int it = 0; it < 4; ++it)
            CP_ASYNC16(bb + (uint32_t)((brb + it * 32) * APAD + c8 * 8) * 2,
                       g_Wpack + (size_t)(brb + it * 32) * DDIM + k0 + c8 * 8);
        CP_COMMIT();
    };

    // ---- prologue: fully stage chunk 0 ----
    issue_B(0);
    ldgA(0, 0); stsA(0, 0);
    ldgA(0, 1); stsA(0, 1);
    CP_WAIT0();

    for (int c = 0; c < NCHUNK; ++c) {
        __syncthreads();                 // A(c),B(c) visible; compute(c-1) retired
        if (c + 1 < NCHUNK) issue_B(c + 1);

        const uint32_t aStage = smem_base + (c & 1) * ABYTES;
        const uint32_t bStage = smem_base + BOFF + (c & 1) * BBYTES;

        uint32_t afr[2][2][4];           // [buf][mt][4]
        uint32_t bfr[2][4];              // [buf][4] = {b0a,b1a,b0b,b1b}

        // preload frags for j=0
        {
            const uint32_t kOff = (uint32_t)((wstag & 3) << 5);
            LDSM_X4(afr[0][0], aStage + aLdsmBase + kOff);
            LDSM_X4(afr[0][1], aStage + aLdsmBase + (uint32_t)(16 * APAD * 2) + kOff);
            LDSM_X4(bfr[0],    bStage + bLdsmBase + kOff);
        }

        #pragma unroll
        for (int j = 0; j < 4; ++j) {
            const uint32_t kOff  = (uint32_t)((((j + wstag) & 3)) << 5);
            const uint32_t kOffN = (uint32_t)((((j + 1 + wstag) & 3)) << 5);
            #pragma unroll
            for (int pr = 0; pr < 4; ++pr) {
                const int cur = pr & 1;          // (j*4+pr)&1 with 4 | per j
                const int nxt = cur ^ 1;
                if (pr < 3) {
                    LDSM_X4(bfr[nxt],
                            bStage + bLdsmBase + (uint32_t)((pr + 1) * 16 * APAD * 2) + kOff);
                } else if (j < 3) {
                    LDSM_X4(afr[(j + 1) & 1][0], aStage + aLdsmBase + kOffN);
                    LDSM_X4(afr[(j + 1) & 1][1],
                            aStage + aLdsmBase + (uint32_t)(16 * APAD * 2) + kOffN);
                    LDSM_X4(bfr[nxt], bStage + bLdsmBase + kOffN);
                }
                #pragma unroll
                for (int mt = 0; mt < 2; ++mt) {
                    MMA(acc[mt][2 * pr],     afr[j & 1][mt], bfr[cur][0], bfr[cur][1]);
                    MMA(acc[mt][2 * pr + 1], afr[j & 1][mt], bfr[cur][2], bfr[cur][3]);
                }
            }
            // ---- A(c+1) staging slotted between j-steps (buffer (c+1)&1 is free) ----
            if (c + 1 < NCHUNK) {
                if (j == 0)      ldgA(c + 1, 0);
                else if (j == 1) { stsA(c + 1, 0); ldgA(c + 1, 1); }
                else if (j == 2) stsA(c + 1, 1);
            }
        }
        if (c + 1 < NCHUNK) CP_WAIT0();   // B(c+1) landed (issued a full chunk ago)
    }
    __syncthreads();   // MMAs done; stage buffers dead -> reuse smem as outS

    // --- scatter accumulators to fp32 out tile ---
    #pragma unroll
    for (int mt = 0; mt < 2; ++mt) {
        #pragma unroll
        for (int nt = 0; nt < 8; ++nt) {
            const int r = warp_m + mt * 16 + gid;
            const int col = warp_n + nt * 8 + tig * 2;
            *reinterpret_cast<float2*>(outS + r * OPAD + col) =
                make_float2(acc[mt][nt][0], acc[mt][nt][1]);
            *reinterpret_cast<float2*>(outS + (r + 8) * OPAD + col) =
                make_float2(acc[mt][nt][2], acc[mt][nt][3]);
        }
    }
    __syncthreads();

    // --- per-row epilogue: softmax gates, expert mix, sigmoid heads ---
    if (tid < TILE_M) {
        const float* rowv = outS + tid * OPAD;

        float g[2][10];
        #pragma unroll
        for (int t = 0; t < 2; ++t) {
            float s = 0.0f;
            #pragma unroll
            for (int e = 0; e < 10; ++e) {
                float l = rowv[100 + t * 10 + e] + gate_b[t * 10 + e];
                float ex = expf(l);
                g[t][e] = ex; s += ex;
            }
            float inv = 1.0f / s;
            #pragma unroll
            for (int e = 0; e < 10; ++e) g[t][e] *= inv;
        }

        float ti0[10], ti1[10];
        #pragma unroll
        for (int u = 0; u < 10; ++u) { ti0[u] = 0.0f; ti1[u] = 0.0f; }
        #pragma unroll
        for (int e = 0; e < 10; ++e) {
            const float g0 = g[0][e], g1 = g[1][e];
            #pragma unroll
            for (int u = 0; u < 10; ++u) {
                const int j = e * 10 + u;
                float v = fmaxf(rowv[j] + expert_b[j], 0.0f);
                ti0[u] += v * g0;
                ti1[u] += v * g1;
            }
        }

        float zc = ctr_b[0], zv = cvr_b[0];
        #pragma unroll
        for (int u = 0; u < 10; ++u) {
            zc += ti0[u] * ctr_w[u];
            zv += ti1[u] * cvr_w[u];
        }
        const int gr = row0 + tid;
        out[gr]         = 1.0f / (1.0f + expf(-zc));
        out[BROWS + gr] = 1.0f / (1.0f + expf(-zv));
    }
}

// ---------------- launch ----------------
extern "C" void kernel_launch(void* const* d_in, const int* in_sizes, int n_in,
                              void* d_out, int out_size) {
    const float* x        = (const float*)d_in[0];
    const float* expert_w = (const float*)d_in[3];
    const float* expert_b = (const float*)d_in[4];
    const float* gate_w   = (const float*)d_in[5];
    const float* gate_b   = (const float*)d_in[6];
    const float* ctr_w    = (const float*)d_in[7];
    const float* ctr_b    = (const float*)d_in[8];
    const float* cvr_w    = (const float*)d_in[9];
    const float* cvr_b    = (const float*)d_in[10];
    float* out = (float*)d_out;

    cudaFuncSetAttribute(mmoe_main_kernel,
                         cudaFuncAttributeMaxDynamicSharedMemorySize, SMEM_BYTES);

    pack_weights_kernel<<<dim3(12, 4), 256>>>(expert_w, gate_w);
    mmoe_main_kernel<<<BROWS / TILE_M, 256, SMEM_BYTES>>>(
        x, expert_b, gate_b, ctr_w, ctr_b, cvr_w, cvr_b, out);
}

// round 15
// speedup vs baseline: 1.2868x; 1.0140x over previous
#include <cuda_runtime.h>
#include <cuda_bf16.h>
#include <cstdint>

// ---------------- problem constants ----------------
#define BROWS   65536
#define DDIM    1024
#define NCOLS   128      // 120 real columns padded to 128
#define KC      64       // K elems staged per chunk
#define NCHUNK  (DDIM / KC)   // 16
#define TILE_M  128
#define APAD    72       // smem row pitch (bf16): 144B rows -> conflict-free LDSM
#define OPAD    130      // out-tile row pitch (floats)

#define ABYTES  (TILE_M * APAD * 2)     // 18432 per A stage
#define BOFF    (2 * ABYTES)            // 36864
#define BHALF   (64 * APAD * 2)         // 9216: one n-group B copy per stage
#define SMEM_BYTES (BOFF + 2 * 2 * BHALF)  // 73728 (>= out tile 66560)

// packed weights: [NCOLS][DDIM] K-major bf16 (static device array — no alloc)
// rows 120..127 never written: __device__ globals are zero-initialized.
__device__ __align__(16) __nv_bfloat16 g_Wpack[NCOLS * DDIM];

__device__ __forceinline__ uint32_t smem_u32(const void* p) {
    uint32_t a;
    asm("{ .reg .u64 t; cvta.to.shared.u64 t, %1; cvt.u32.u64 %0, t; }" : "=r"(a) : "l"(p));
    return a;
}
#define CP_ASYNC16(dst_u32, src_ptr) \
    asm volatile("cp.async.cg.shared.global [%0], [%1], 16;" :: "r"(dst_u32), "l"(src_ptr) : "memory")
#define CP_COMMIT() asm volatile("cp.async.commit_group;" ::: "memory")
#define CP_WAIT0()  asm volatile("cp.async.wait_group 0;" ::: "memory")
#define LDSM_X4(r, addr) \
    asm volatile("ldmatrix.sync.aligned.m8n8.x4.shared.b16 {%0,%1,%2,%3}, [%4];" \
                 : "=r"((r)[0]), "=r"((r)[1]), "=r"((r)[2]), "=r"((r)[3]) : "r"(addr))
#define MMA(d, a, b0, b1) \
    asm volatile("mma.sync.aligned.m16n8k16.row.col.f32.bf16.bf16.f32 " \
                 "{%0,%1,%2,%3}, {%4,%5,%6,%7}, {%8,%9}, {%0,%1,%2,%3};" \
                 : "+f"((d)[0]), "+f"((d)[1]), "+f"((d)[2]), "+f"((d)[3]) \
                 : "r"((a)[0]), "r"((a)[1]), "r"((a)[2]), "r"((a)[3]), "r"(b0), "r"(b1))
// group-local named barriers (id 0 reserved for __syncthreads)
#define BARG(id, cnt) asm volatile("bar.sync %0, %1;" :: "r"(id), "r"(cnt) : "memory")

// ---------------- weight pack kernel ----------------
__global__ void pack_weights_kernel(const float* __restrict__ expert_w,
                                    const float* __restrict__ gate_w) {
    __shared__ float s[256][10];
    const int bx = blockIdx.x;
    const int d0 = blockIdx.y * 256;
    const int tid = threadIdx.x;
    const float* src = (bx < 10) ? expert_w + (size_t)bx * DDIM * 10
                                 : gate_w   + (size_t)(bx - 10) * DDIM * 10;
    #pragma unroll
    for (int k = 0; k < 10; ++k) {
        int idx = tid + k * 256;
        s[idx / 10][idx % 10] = src[(size_t)d0 * 10 + idx];
    }
    __syncthreads();
    const int j0 = (bx < 10) ? bx * 10 : 100 + (bx - 10) * 10;
    #pragma unroll
    for (int r = 0; r < 10; ++r)
        g_Wpack[(size_t)(j0 + r) * DDIM + d0 + tid] = __float2bfloat16(s[tid][r]);
}

// ---------------- fused MMoE main kernel (group-decoupled sync) ---------------
extern "C" __global__ void __launch_bounds__(256, 2)
mmoe_main_kernel(const float* __restrict__ x,
                 const float* __restrict__ expert_b,   // [10,10]
                 const float* __restrict__ gate_b,     // [2,10]
                 const float* __restrict__ ctr_w,      // [10]
                 const float* __restrict__ ctr_b,      // [1]
                 const float* __restrict__ cvr_w,      // [10]
                 const float* __restrict__ cvr_b,      // [1]
                 float* __restrict__ out) {            // [2*B] = [ctr | cvr]
    extern __shared__ char smem[];
    const uint32_t smem_base = smem_u32(smem);
    float* outS = reinterpret_cast<float*>(smem);

    const int tid  = threadIdx.x;
    const int wid  = tid >> 5;
    const int lane = tid & 31;
    const int gid  = lane >> 2;
    const int tig  = lane & 3;
    const int mi   = wid & 3;             // 4 warps along M
    const int ni   = wid >> 2;            // 2 warps along N
    const int warp_m = mi * 32;
    const int warp_n = ni * 64;
    const int row0 = blockIdx.x * TILE_M;
    const int wstag = wid & 3;

    // A-group (2 warps: mi, mi+4) lane id 0..63; B-group (4 warps, same ni) lane id 0..127
    const int agid = lane + ni * 32;
    const int btid = lane + mi * 32;

    // LDSM bases
    const uint32_t aLdsmBase =
        (uint32_t)(warp_m + ((lane >> 3) & 1) * 8 + (lane & 7)) * (APAD * 2)
        + ((lane >> 4) & 1) * 16;
    const uint32_t bLdsmBase =                         // local rows of own B copy
        (uint32_t)(((lane >> 4) & 1) * 8 + (lane & 7)) * (APAD * 2)
        + ((lane >> 3) & 1) * 16;

    float acc[2][8][4];
    #pragma unroll
    for (int mt = 0; mt < 2; ++mt)
        #pragma unroll
        for (int nt = 0; nt < 8; ++nt)
            #pragma unroll
            for (int i = 0; i < 4; ++i) acc[mt][nt][i] = 0.0f;

    // A staging: this warp's group stages rows [32mi, 32mi+32). Per lane 8 float4:
    // row = 32mi + (agid>>4) + 4*it, col = (agid&15)*4
    float4 av[8];
    const int arow = (agid >> 4);         // 0..3
    const int ac4  = agid & 15;

    auto ldgA = [&](int c) {
        const int k0 = c * KC;
        #pragma unroll
        for (int it = 0; it < 8; ++it)
            av[it] = *reinterpret_cast<const float4*>(
                x + (size_t)(row0 + warp_m + arow + it * 4) * DDIM + k0 + ac4 * 4);
    };
    auto stsA = [&](int c) {
        __nv_bfloat16* Ab = reinterpret_cast<__nv_bfloat16*>(smem + (c & 1) * ABYTES);
        #pragma unroll
        for (int it = 0; it < 8; ++it) {
            __nv_bfloat162 lo = __floats2bfloat162_rn(av[it].x, av[it].y);
            __nv_bfloat162 hi = __floats2bfloat162_rn(av[it].z, av[it].w);
            uint2 pk;
            pk.x = *reinterpret_cast<uint32_t*>(&lo);
            pk.y = *reinterpret_cast<uint32_t*>(&hi);
            *reinterpret_cast<uint2*>(Ab + (warp_m + arow + it * 4) * APAD + ac4 * 4) = pk;
        }
    };
    auto issue_B = [&](int c) {           // stage own n-group's 64-row B slice copy
        const int k0 = c * KC;
        const uint32_t bb = smem_base + BOFF + (c & 1) * (2 * BHALF) + ni * BHALF;
        #pragma unroll
        for (int it = 0; it < 4; ++it) {
            const int idx = btid + it * 128;          // 0..511
            const int row = idx >> 3, c8 = idx & 7;   // local row 0..63
            CP_ASYNC16(bb + (uint32_t)(row * APAD + c8 * 8) * 2,
                       g_Wpack + (size_t)(warp_n + row) * DDIM + k0 + c8 * 8);
        }
        CP_COMMIT();
    };
    auto compute_kt = [&](int c, int j) {
        const uint32_t aStage = smem_base + (c & 1) * ABYTES;
        const uint32_t bStage = smem_base + BOFF + (c & 1) * (2 * BHALF) + ni * BHALF;
        const uint32_t kOff = (uint32_t)((((j + wstag) & 3)) << 5);

        uint32_t afrag[2][4];
        #pragma unroll
        for (int mt = 0; mt < 2; ++mt)
            LDSM_X4(afrag[mt],
                    aStage + aLdsmBase + (uint32_t)(mt * 16 * APAD * 2) + kOff);

        #pragma unroll
        for (int pr = 0; pr < 4; ++pr) {
            uint32_t bfr[4];
            LDSM_X4(bfr, bStage + bLdsmBase + (uint32_t)(pr * 16 * APAD * 2) + kOff);
            #pragma unroll
            for (int mt = 0; mt < 2; ++mt) {
                MMA(acc[mt][2 * pr],     afrag[mt], bfr[0], bfr[1]);
                MMA(acc[mt][2 * pr + 1], afrag[mt], bfr[2], bfr[3]);
            }
        }
    };

    // ---- prologue: stage chunk 0; preload av = A(1) ----
    ldgA(0);
    issue_B(0);
    stsA(0);
    ldgA(1);
    CP_WAIT0();

    // ---- mainloop: group-local barriers only ----
    for (int c = 0; c < NCHUNK; ++c) {
        BARG(1 + mi, 64);                 // A group: stage(c) visible, compute(c-1) done
        BARG(5 + ni, 128);                // B group: copy(c) landed,  compute(c-1) done

        if (c + 1 < NCHUNK) issue_B(c + 1);   // buffer (c+1)&1 freed by the barriers
        compute_kt(c, 0);
        if (c + 1 < NCHUNK) stsA(c + 1);      // av holds A(c+1), loaded a chunk ago
        compute_kt(c, 1);
        if (c + 2 < NCHUNK) ldgA(c + 2);      // av free after STS
        compute_kt(c, 2);
        compute_kt(c, 3);
        if (c + 1 < NCHUNK) CP_WAIT0();       // own B(c+1) ops landed
    }
    __syncthreads();   // ring dead -> reuse smem as outS

    // --- scatter accumulators to fp32 out tile ---
    #pragma unroll
    for (int mt = 0; mt < 2; ++mt) {
        #pragma unroll
        for (int nt = 0; nt < 8; ++nt) {
            const int r = warp_m + mt * 16 + gid;
            const int col = warp_n + nt * 8 + tig * 2;
            *reinterpret_cast<float2*>(outS + r * OPAD + col) =
                make_float2(acc[mt][nt][0], acc[mt][nt][1]);
            *reinterpret_cast<float2*>(outS + (r + 8) * OPAD + col) =
                make_float2(acc[mt][nt][2], acc[mt][nt][3]);
        }
    }
    __syncthreads();

    // --- per-row epilogue: softmax gates, expert mix, sigmoid heads ---
    if (tid < TILE_M) {
        const float* rowv = outS + tid * OPAD;

        float g[2][10];
        #pragma unroll
        for (int t = 0; t < 2; ++t) {
            float s = 0.0f;
            #pragma unroll
            for (int e = 0; e < 10; ++e) {
                float l = rowv[100 + t * 10 + e] + gate_b[t * 10 + e];
                float ex = expf(l);
                g[t][e] = ex; s += ex;
            }
            float inv = 1.0f / s;
            #pragma unroll
            for (int e = 0; e < 10; ++e) g[t][e] *= inv;
        }

        float ti0[10], ti1[10];
        #pragma unroll
        for (int u = 0; u < 10; ++u) { ti0[u] = 0.0f; ti1[u] = 0.0f; }
        #pragma unroll
        for (int e = 0; e < 10; ++e) {
            const float g0 = g[0][e], g1 = g[1][e];
            #pragma unroll
            for (int u = 0; u < 10; ++u) {
                const int j = e * 10 + u;
                float v = fmaxf(rowv[j] + expert_b[j], 0.0f);
                ti0[u] += v * g0;
                ti1[u] += v * g1;
            }
        }

        float zc = ctr_b[0], zv = cvr_b[0];
        #pragma unroll
        for (int u = 0; u < 10; ++u) {
            zc += ti0[u] * ctr_w[u];
            zv += ti1[u] * cvr_w[u];
        }
        const int gr = row0 + tid;
        out[gr]         = 1.0f / (1.0f + expf(-zc));
        out[BROWS + gr] = 1.0f / (1.0f + expf(-zv));
    }
}

// ---------------- launch ----------------
extern "C" void kernel_launch(void* const* d_in, const int* in_sizes, int n_in,
                              void* d_out, int out_size) {
    const float* x        = (const float*)d_in[0];
    const float* expert_w = (const float*)d_in[3];
    const float* expert_b = (const float*)d_in[4];
    const float* gate_w   = (const float*)d_in[5];
    const float* gate_b   = (const float*)d_in[6];
    const float* ctr_w    = (const float*)d_in[7];
    const float* ctr_b    = (const float*)d_in[8];
    const float* cvr_w    = (const float*)d_in[9];
    const float* cvr_b    = (const float*)d_in[10];
    float* out = (float*)d_out;

    cudaFuncSetAttribute(mmoe_main_kernel,
                         cudaFuncAttributeMaxDynamicSharedMemorySize, SMEM_BYTES);

    pack_weights_kernel<<<dim3(12, 4), 256>>>(expert_w, gate_w);
    mmoe_main_kernel<<<BROWS / TILE_M, 256, SMEM_BYTES>>>(
        x, expert_b, gate_b, ctr_w, ctr_b, cvr_w, cvr_b, out);
}